// round 1
// baseline (speedup 1.0000x reference)
#include <cuda_runtime.h>
#include <cuda_bf16.h>
#include <math.h>

// Problem constants
#define BB 32
#define CC 512
#define HW 1024
#define DD 64
#define OO 640   // 2*D + C

// ---------------- scratch (device globals; no allocation allowed) ----------------
__device__ float g_qkv[BB * OO * HW];            // 80 MB
__device__ float g_beta[(size_t)BB * HW * HW];   // 128 MB (raw scores)
__device__ float g_xr[BB * CC * HW];             // 64 MB
__device__ float g_z[BB * CC * HW];              // 64 MB
__device__ float g_scale1[CC], g_shift1[CC], g_scale2[CC], g_shift2[CC];
__device__ float g_pmax[BB * 4 * HW], g_psum[BB * 4 * HW];
__device__ float g_cmax[BB * HW], g_cinv[BB * HW];

// ---------------- fast exp (FMA pipe only; MUFU is slow on sm_103a) ----------------
__device__ __forceinline__ float fexp(float x) {
    x = fmaxf(x, -87.0f);
    float t  = x * 1.4426950408889634f;
    float fi = floorf(t);
    float f  = t - fi;
    // degree-6 Taylor of 2^f on [0,1): rel err ~1.5e-5
    float r = 1.5403530e-4f;
    r = fmaf(r, f, 1.3333558e-3f);
    r = fmaf(r, f, 9.6181291e-3f);
    r = fmaf(r, f, 5.5504109e-2f);
    r = fmaf(r, f, 2.4022651e-1f);
    r = fmaf(r, f, 6.9314718e-1f);
    r = fmaf(r, f, 1.0f);
    return r * __int_as_float(((int)fi + 127) << 23);
}

// ---------------- per-channel batchnorm stats: scale/shift ----------------
__global__ void bn_stats_kernel(const float* __restrict__ x,
                                const float* __restrict__ gamma,
                                const float* __restrict__ beta,
                                float* __restrict__ scale,
                                float* __restrict__ shift) {
    int c = blockIdx.x;
    int tid = threadIdx.x;
    float s = 0.f, s2 = 0.f;
    const float* xc = x + (size_t)c * HW;
    for (int b = 0; b < BB; b++) {
        const float* p = xc + (size_t)b * CC * HW;
        #pragma unroll 4
        for (int i = tid; i < HW; i += 256) {
            float v = p[i];
            s += v; s2 = fmaf(v, v, s2);
        }
    }
    __shared__ float ss[256], ss2[256];
    ss[tid] = s; ss2[tid] = s2;
    __syncthreads();
    for (int o = 128; o > 0; o >>= 1) {
        if (tid < o) { ss[tid] += ss[tid + o]; ss2[tid] += ss2[tid + o]; }
        __syncthreads();
    }
    if (tid == 0) {
        const float invN = 1.0f / (BB * HW);
        float mean = ss[0] * invN;
        float var  = ss2[0] * invN - mean * mean;
        float sc = gamma[c] * rsqrtf(var + 1e-5f);
        scale[c] = sc;
        shift[c] = beta[c] - mean * sc;
    }
}

// ---------------- softmax column stats (axis=q) on raw scores ----------------
// partial over q-chunks of 256
__global__ void softmax_partial(const float* __restrict__ beta,
                                float* __restrict__ pmax, float* __restrict__ psum) {
    int b = blockIdx.z, qb = blockIdx.y;
    int k = blockIdx.x * 256 + threadIdx.x;
    const float* p = beta + ((size_t)b << 20) + (size_t)(qb * 256) * HW + k;
    float m = -3.0e38f, s = 0.f;
    #pragma unroll 8
    for (int q = 0; q < 256; q++) {
        float v  = p[(size_t)q * HW];
        float nm = fmaxf(m, v);
        s = fmaf(s, fexp(m - nm), fexp(v - nm));
        m = nm;
    }
    int idx = ((b * 4 + qb) << 10) + k;
    pmax[idx] = m; psum[idx] = s;
}

__global__ void softmax_combine(const float* __restrict__ pmax,
                                const float* __restrict__ psum,
                                float* __restrict__ cmax, float* __restrict__ cinv) {
    int b = blockIdx.y;
    int k = blockIdx.x * 256 + threadIdx.x;
    float mv[4], sv[4];
    float m = -3.0e38f;
    #pragma unroll
    for (int qb = 0; qb < 4; qb++) {
        int idx = ((b * 4 + qb) << 10) + k;
        mv[qb] = pmax[idx]; sv[qb] = psum[idx];
        m = fmaxf(m, mv[qb]);
    }
    float s = 0.f;
    #pragma unroll
    for (int qb = 0; qb < 4; qb++) s = fmaf(sv[qb], fexp(mv[qb] - m), s);
    cmax[(b << 10) + k] = m;
    cinv[(b << 10) + k] = 1.0f / s;
}

// ---------------- generic batched SGEMM with fused pre/post ops ----------------
// Flags
#define F_TA     1    // A[m,k] = A[k*lda + m]
#define F_BAFF   2    // B elem: v*bsc[k]+bsh[k]
#define F_BRELU  4    // B elem: relu
#define F_BEXP   8    // B elem: fexp(v - colmax[n])
#define F_EBIAS  16   // + bias[m]
#define F_ERELU  32   // relu output
#define F_ERES   64   // + res[m,n]
#define F_ECOL   128  // * colinv[n]

template <int F>
__global__ void __launch_bounds__(256, 2) gemm_k(
    const float* __restrict__ A, const float* __restrict__ B, float* __restrict__ C,
    int M, int N, int K, int lda, int ldb, int ldc,
    long sA, long sB, long sC,
    const float* __restrict__ bsc, const float* __restrict__ bsh,
    const float* __restrict__ bias,
    const float* __restrict__ res, long sRes,
    const float* __restrict__ colmax, const float* __restrict__ colinv,
    float alpha)
{
    constexpr bool TA    = (F & F_TA)    != 0;
    constexpr bool BAFF  = (F & F_BAFF)  != 0;
    constexpr bool BRELU = (F & F_BRELU) != 0;
    constexpr bool BEXP  = (F & F_BEXP)  != 0;
    constexpr bool EBIAS = (F & F_EBIAS) != 0;
    constexpr bool ERELU = (F & F_ERELU) != 0;
    constexpr bool ERES  = (F & F_ERES)  != 0;
    constexpr bool ECOL  = (F & F_ECOL)  != 0;

    __shared__ float As[16][128];
    __shared__ float Bs[16][128];
    __shared__ float cms[128];

    const int bz = blockIdx.z;
    const int n0 = blockIdx.x * 128;
    const int m0 = blockIdx.y * 128;
    const int tid = threadIdx.x;
    const int tx = tid & 15;
    const int ty = tid >> 4;

    const float* Ab = A + (size_t)bz * sA;
    const float* Bb = B + (size_t)bz * sB;

    if (BEXP) {
        if (tid < 128) cms[tid] = colmax[(size_t)bz * N + n0 + tid];
        __syncthreads();
    }

    float acc[8][8];
    #pragma unroll
    for (int i = 0; i < 8; i++)
        #pragma unroll
        for (int j = 0; j < 8; j++) acc[i][j] = 0.f;

    for (int k0 = 0; k0 < K; k0 += 16) {
        if (!TA) {
            int r  = tid >> 2;
            int c4 = (tid & 3) << 2;
            #pragma unroll
            for (int h = 0; h < 2; h++) {
                int row = r + h * 64;
                float4 v = *(const float4*)(Ab + (size_t)(m0 + row) * lda + (k0 + c4));
                As[c4 + 0][row] = v.x; As[c4 + 1][row] = v.y;
                As[c4 + 2][row] = v.z; As[c4 + 3][row] = v.w;
            }
        } else {
            int kr = tid >> 5;
            int m4 = (tid & 31) << 2;
            #pragma unroll
            for (int h = 0; h < 2; h++) {
                int kk = kr + h * 8;
                *(float4*)&As[kk][m4] =
                    *(const float4*)(Ab + (size_t)(k0 + kk) * lda + (m0 + m4));
            }
        }
        {
            int kr = tid >> 5;
            int n4 = (tid & 31) << 2;
            #pragma unroll
            for (int h = 0; h < 2; h++) {
                int kk = kr + h * 8;
                float4 v = *(const float4*)(Bb + (size_t)(k0 + kk) * ldb + (n0 + n4));
                if (BAFF) {
                    float sc = bsc[k0 + kk], sh = bsh[k0 + kk];
                    v.x = fmaf(v.x, sc, sh); v.y = fmaf(v.y, sc, sh);
                    v.z = fmaf(v.z, sc, sh); v.w = fmaf(v.w, sc, sh);
                }
                if (BRELU) {
                    v.x = fmaxf(v.x, 0.f); v.y = fmaxf(v.y, 0.f);
                    v.z = fmaxf(v.z, 0.f); v.w = fmaxf(v.w, 0.f);
                }
                if (BEXP) {
                    v.x = fexp(v.x - cms[n4 + 0]); v.y = fexp(v.y - cms[n4 + 1]);
                    v.z = fexp(v.z - cms[n4 + 2]); v.w = fexp(v.w - cms[n4 + 3]);
                }
                *(float4*)&Bs[kk][n4] = v;
            }
        }
        __syncthreads();
        #pragma unroll
        for (int kk = 0; kk < 16; kk++) {
            float a[8], bfr[8];
            *(float4*)&a[0]   = *(const float4*)&As[kk][ty << 2];
            *(float4*)&a[4]   = *(const float4*)&As[kk][64 + (ty << 2)];
            *(float4*)&bfr[0] = *(const float4*)&Bs[kk][tx << 2];
            *(float4*)&bfr[4] = *(const float4*)&Bs[kk][64 + (tx << 2)];
            #pragma unroll
            for (int i = 0; i < 8; i++)
                #pragma unroll
                for (int j = 0; j < 8; j++)
                    acc[i][j] = fmaf(a[i], bfr[j], acc[i][j]);
        }
        __syncthreads();
    }

    float* Cb = C + (size_t)bz * sC;
    const float* Rb = ERES ? (res + (size_t)bz * sRes) : nullptr;
    #pragma unroll
    for (int i = 0; i < 8; i++) {
        int mr = m0 + ((i < 4) ? ((ty << 2) + i) : (64 + (ty << 2) + (i - 4)));
        float bi = EBIAS ? bias[mr] : 0.f;
        #pragma unroll
        for (int jh = 0; jh < 2; jh++) {
            int nc = n0 + jh * 64 + (tx << 2);
            float4 v;
            v.x = acc[i][jh * 4 + 0] * alpha;
            v.y = acc[i][jh * 4 + 1] * alpha;
            v.z = acc[i][jh * 4 + 2] * alpha;
            v.w = acc[i][jh * 4 + 3] * alpha;
            if (EBIAS) { v.x += bi; v.y += bi; v.z += bi; v.w += bi; }
            if (ECOL) {
                const float* cv = colinv + (size_t)bz * N + nc;
                v.x *= cv[0]; v.y *= cv[1]; v.z *= cv[2]; v.w *= cv[3];
            }
            if (ERELU) {
                v.x = fmaxf(v.x, 0.f); v.y = fmaxf(v.y, 0.f);
                v.z = fmaxf(v.z, 0.f); v.w = fmaxf(v.w, 0.f);
            }
            if (ERES) {
                float4 r4 = *(const float4*)(Rb + (size_t)mr * ldc + nc);
                v.x += r4.x; v.y += r4.y; v.z += r4.z; v.w += r4.w;
            }
            *(float4*)(Cb + (size_t)mr * ldc + nc) = v;
        }
    }
}

// ---------------- launcher ----------------
extern "C" void kernel_launch(void* const* d_in, const int* in_sizes, int n_in,
                              void* d_out, int out_size) {
    const float* x     = (const float*)d_in[0];
    const float* bn1_g = (const float*)d_in[1];
    const float* bn1_b = (const float*)d_in[2];
    const float* W_qkv = (const float*)d_in[3];
    const float* b_qkv = (const float*)d_in[4];
    const float* bn2_g = (const float*)d_in[5];
    const float* bn2_b = (const float*)d_in[6];
    const float* W1    = (const float*)d_in[7];
    const float* b1    = (const float*)d_in[8];
    const float* W2    = (const float*)d_in[9];
    const float* b2    = (const float*)d_in[10];
    float* out = (float*)d_out;

    float *p_qkv, *p_beta, *p_xr, *p_z;
    float *p_s1, *p_h1, *p_s2, *p_h2;
    float *p_pmax, *p_psum, *p_cmax, *p_cinv;
    cudaGetSymbolAddress((void**)&p_qkv,  g_qkv);
    cudaGetSymbolAddress((void**)&p_beta, g_beta);
    cudaGetSymbolAddress((void**)&p_xr,   g_xr);
    cudaGetSymbolAddress((void**)&p_z,    g_z);
    cudaGetSymbolAddress((void**)&p_s1,   g_scale1);
    cudaGetSymbolAddress((void**)&p_h1,   g_shift1);
    cudaGetSymbolAddress((void**)&p_s2,   g_scale2);
    cudaGetSymbolAddress((void**)&p_h2,   g_shift2);
    cudaGetSymbolAddress((void**)&p_pmax, g_pmax);
    cudaGetSymbolAddress((void**)&p_psum, g_psum);
    cudaGetSymbolAddress((void**)&p_cmax, g_cmax);
    cudaGetSymbolAddress((void**)&p_cinv, g_cinv);

    // 1) bn1 per-channel scale/shift
    bn_stats_kernel<<<CC, 256>>>(x, bn1_g, bn1_b, p_s1, p_h1);

    // 2) qkv = W_qkv @ relu(bn1(x)) + b_qkv   [M=640, N=1024, K=512] x32
    gemm_k<F_BAFF | F_BRELU | F_EBIAS><<<dim3(8, 5, BB), 256>>>(
        W_qkv, x, p_qkv, OO, HW, CC, CC, HW, HW,
        0L, (long)CC * HW, (long)OO * HW,
        p_s1, p_h1, b_qkv, nullptr, 0L, nullptr, nullptr, 1.0f);

    // 3) raw scores S = (Q^T K)/8   [M=1024, N=1024, K=64] x32
    gemm_k<F_TA><<<dim3(8, 8, BB), 256>>>(
        p_qkv, p_qkv + DD * HW, p_beta, HW, HW, DD, HW, HW, HW,
        (long)OO * HW, (long)OO * HW, (long)HW * HW,
        nullptr, nullptr, nullptr, nullptr, 0L, nullptr, nullptr, 0.125f);

    // 4) column softmax stats (axis=q): max + sum(exp)
    softmax_partial<<<dim3(4, 4, BB), 256>>>(p_beta, p_pmax, p_psum);
    softmax_combine<<<dim3(4, BB), 256>>>(p_pmax, p_psum, p_cmax, p_cinv);

    // 5) xr = x + V @ softmax(S): B-load applies exp(S - max[n]); epilogue * 1/sum[n] + x
    gemm_k<F_BEXP | F_ECOL | F_ERES><<<dim3(8, 4, BB), 256>>>(
        p_qkv + 2 * DD * HW, p_beta, p_xr, CC, HW, HW, HW, HW, HW,
        (long)OO * HW, (long)HW * HW, (long)CC * HW,
        nullptr, nullptr, nullptr, x, (long)CC * HW, p_cmax, p_cinv, 1.0f);

    // 6) bn2 stats on xr
    bn_stats_kernel<<<CC, 256>>>(p_xr, bn2_g, bn2_b, p_s2, p_h2);

    // 7) z = relu(W1 @ bn2(xr) + b1)   [M=512, N=1024, K=512] x32
    gemm_k<F_BAFF | F_EBIAS | F_ERELU><<<dim3(8, 4, BB), 256>>>(
        W1, p_xr, p_z, CC, HW, CC, CC, HW, HW,
        0L, (long)CC * HW, (long)CC * HW,
        p_s2, p_h2, b1, nullptr, 0L, nullptr, nullptr, 1.0f);

    // 8) out = xr + W2 @ z + b2
    gemm_k<F_EBIAS | F_ERES><<<dim3(8, 4, BB), 256>>>(
        W2, p_z, out, CC, HW, CC, CC, HW, HW,
        0L, (long)CC * HW, (long)CC * HW,
        nullptr, nullptr, b2, p_xr, (long)CC * HW, nullptr, nullptr, 1.0f);
}

// round 2
// speedup vs baseline: 2.2224x; 2.2224x over previous
#include <cuda_runtime.h>
#include <cuda_bf16.h>
#include <math.h>

#define BB 32
#define CC 512
#define HW 1024
#define DD 64
#define OO 640   // 2*D + C

// ---------------- scratch (device globals) ----------------
__device__ float g_qkv[BB * OO * HW];            // 80 MB (tf32-rounded Q,K,V)
__device__ float g_beta[(size_t)BB * HW * HW];   // 128 MB (S raw, then P in-place)
__device__ float g_xr[BB * CC * HW];             // 64 MB
__device__ float g_h[BB * CC * HW];              // 64 MB (h1, later h2)
__device__ float g_vt[BB * CC * HW];             // 64 MB (Vt, later reused for z)
__device__ float g_z[BB * CC * HW];              // 64 MB (mlp hidden)
__device__ float g_wqkvt[CC * OO];               // W_qkv^T [512][640]
__device__ float g_w1t[CC * CC];
__device__ float g_w2t[CC * CC];
__device__ float g_scale1[CC], g_shift1[CC], g_scale2[CC], g_shift2[CC];
__device__ float g_pmax[BB * 4 * HW], g_psum[BB * 4 * HW];
__device__ float g_cmax[BB * HW], g_cinv[BB * HW];

// ---------------- helpers ----------------
__device__ __forceinline__ float fexp(float x) {
    x = fmaxf(x, -87.0f);
    float t  = x * 1.4426950408889634f;
    float fi = floorf(t);
    float f  = t - fi;
    float r = 1.5403530e-4f;
    r = fmaf(r, f, 1.3333558e-3f);
    r = fmaf(r, f, 9.6181291e-3f);
    r = fmaf(r, f, 5.5504109e-2f);
    r = fmaf(r, f, 2.4022651e-1f);
    r = fmaf(r, f, 6.9314718e-1f);
    r = fmaf(r, f, 1.0f);
    return r * __int_as_float(((int)fi + 127) << 23);
}

__device__ __forceinline__ float rtf(float x) {  // round-to-nearest tf32
    unsigned u;
    asm("cvt.rna.tf32.f32 %0, %1;" : "=r"(u) : "f"(x));
    return __uint_as_float(u);
}

__device__ __forceinline__ void cpa16(void* s, const void* g) {
    unsigned ss = (unsigned)__cvta_generic_to_shared(s);
    asm volatile("cp.async.cg.shared.global [%0], [%1], 16;\n" :: "r"(ss), "l"(g));
}

__device__ __forceinline__ void mma8(float* c, const unsigned* a, const unsigned* b) {
    asm volatile(
        "mma.sync.aligned.m16n8k8.row.col.f32.tf32.tf32.f32 "
        "{%0,%1,%2,%3}, {%4,%5,%6,%7}, {%8,%9}, {%0,%1,%2,%3};\n"
        : "+f"(c[0]), "+f"(c[1]), "+f"(c[2]), "+f"(c[3])
        : "r"(a[0]), "r"(a[1]), "r"(a[2]), "r"(a[3]), "r"(b[0]), "r"(b[1]));
}

// ---------------- bn stats ----------------
__global__ void bn_stats_kernel(const float* __restrict__ x,
                                const float* __restrict__ gamma,
                                const float* __restrict__ beta,
                                float* __restrict__ scale,
                                float* __restrict__ shift) {
    int c = blockIdx.x;
    int tid = threadIdx.x;
    float s = 0.f, s2 = 0.f;
    const float* xc = x + (size_t)c * HW;
    for (int b = 0; b < BB; b++) {
        const float* p = xc + (size_t)b * CC * HW;
        #pragma unroll 4
        for (int i = tid; i < HW; i += 256) {
            float v = p[i];
            s += v; s2 = fmaf(v, v, s2);
        }
    }
    __shared__ float ss[256], ss2[256];
    ss[tid] = s; ss2[tid] = s2;
    __syncthreads();
    for (int o = 128; o > 0; o >>= 1) {
        if (tid < o) { ss[tid] += ss[tid + o]; ss2[tid] += ss2[tid + o]; }
        __syncthreads();
    }
    if (tid == 0) {
        const float invN = 1.0f / (BB * HW);
        float mean = ss[0] * invN;
        float var  = ss2[0] * invN - mean * mean;
        float sc = gamma[c] * rsqrtf(var + 1e-5f);
        scale[c] = sc;
        shift[c] = beta[c] - mean * sc;
    }
}

// ---------------- bn apply (+optional relu), tf32-rounded ----------------
template <bool RELU>
__global__ void bn_apply(const float* __restrict__ x, const float* __restrict__ sc,
                         const float* __restrict__ sh, float* __restrict__ o) {
    int i = blockIdx.x * 256 + threadIdx.x;  // over total/4
    int c = (i >> 8) & (CC - 1);
    float4 v = ((const float4*)x)[i];
    float s = sc[c], h = sh[c];
    v.x = fmaf(v.x, s, h); v.y = fmaf(v.y, s, h);
    v.z = fmaf(v.z, s, h); v.w = fmaf(v.w, s, h);
    if (RELU) {
        v.x = fmaxf(v.x, 0.f); v.y = fmaxf(v.y, 0.f);
        v.z = fmaxf(v.z, 0.f); v.w = fmaxf(v.w, 0.f);
    }
    v.x = rtf(v.x); v.y = rtf(v.y); v.z = rtf(v.z); v.w = rtf(v.w);
    ((float4*)o)[i] = v;
}

// ---------------- transpose (+tf32 round), batched ----------------
__global__ void transpose_rnd(const float* __restrict__ in, float* __restrict__ out,
                              int rows, int cols, long sIn, long sOut) {
    __shared__ float t[32][33];
    int z = blockIdx.z;
    const float* I = in + (size_t)z * sIn;
    float* O = out + (size_t)z * sOut;
    int c0 = blockIdx.x * 32, r0 = blockIdx.y * 32;
    int x = threadIdx.x, y = threadIdx.y;  // 32x8
    #pragma unroll
    for (int j = 0; j < 32; j += 8)
        t[y + j][x] = I[(size_t)(r0 + y + j) * cols + c0 + x];
    __syncthreads();
    #pragma unroll
    for (int j = 0; j < 32; j += 8)
        O[(size_t)(c0 + y + j) * rows + r0 + x] = rtf(t[x][y + j]);
}

// ---------------- softmax column stats (axis=q), 4 ILP chains ----------------
__global__ void softmax_partial(const float* __restrict__ beta,
                                float* __restrict__ pmax, float* __restrict__ psum) {
    int b = blockIdx.z, qb = blockIdx.y;
    int k = blockIdx.x * 256 + threadIdx.x;
    const float* p = beta + ((size_t)b << 20) + (size_t)(qb * 256) * HW + k;
    float m[4] = {-3.0e38f, -3.0e38f, -3.0e38f, -3.0e38f};
    float s[4] = {0.f, 0.f, 0.f, 0.f};
    #pragma unroll 2
    for (int q = 0; q < 256; q += 4) {
        #pragma unroll
        for (int j = 0; j < 4; j++) {
            float v  = p[(size_t)(q + j) * HW];
            float nm = fmaxf(m[j], v);
            s[j] = fmaf(s[j], fexp(m[j] - nm), fexp(v - nm));
            m[j] = nm;
        }
    }
    float mm = fmaxf(fmaxf(m[0], m[1]), fmaxf(m[2], m[3]));
    float sm = 0.f;
    #pragma unroll
    for (int j = 0; j < 4; j++) sm = fmaf(s[j], fexp(m[j] - mm), sm);
    int idx = ((b * 4 + qb) << 10) + k;
    pmax[idx] = mm; psum[idx] = sm;
}

__global__ void softmax_combine(const float* __restrict__ pmax,
                                const float* __restrict__ psum,
                                float* __restrict__ cmax, float* __restrict__ cinv) {
    int b = blockIdx.y;
    int k = blockIdx.x * 256 + threadIdx.x;
    float mv[4], sv[4];
    float m = -3.0e38f;
    #pragma unroll
    for (int qb = 0; qb < 4; qb++) {
        int idx = ((b * 4 + qb) << 10) + k;
        mv[qb] = pmax[idx]; sv[qb] = psum[idx];
        m = fmaxf(m, mv[qb]);
    }
    float s = 0.f;
    #pragma unroll
    for (int qb = 0; qb < 4; qb++) s = fmaf(sv[qb], fexp(mv[qb] - m), s);
    cmax[(b << 10) + k] = m;
    cinv[(b << 10) + k] = 1.0f / s;
}

// ---------------- P = rtf(exp(S - max)*inv), in place ----------------
__global__ void p_apply(float* __restrict__ S, const float* __restrict__ cmax,
                        const float* __restrict__ cinv) {
    int i = blockIdx.x * 256 + threadIdx.x;  // over 8388608 float4s
    int b = i >> 18;
    int kk = i & 255;
    float4 v = ((float4*)S)[i];
    float4 m  = ((const float4*)(cmax + ((size_t)b << 10)))[kk];
    float4 iv = ((const float4*)(cinv + ((size_t)b << 10)))[kk];
    v.x = rtf(fexp(v.x - m.x) * iv.x);
    v.y = rtf(fexp(v.y - m.y) * iv.y);
    v.z = rtf(fexp(v.z - m.z) * iv.z);
    v.w = rtf(fexp(v.w - m.w) * iv.w);
    ((float4*)S)[i] = v;
}

// ---------------- tf32 tensor-core GEMM ----------------
// C[m,n] = alpha * sum_k A[k,m]*B[k,n]  (A,B stored k-major, pre-rounded to tf32)
// CTA tile 128x256, 8 warps of 64x64, K-stage 16, cp.async double buffer.
#define F_EBIAS  1
#define F_ERELU  2
#define F_ERES   4
#define F_EROUND 8

#define ASTR 136   // 128 + 8 pad (8 mod 32 -> conflict-free frags)
#define BSTR 264   // 256 + 8 pad
#define ASTAGE (16 * ASTR)
#define BSTAGE (16 * BSTR)
#define SMEM_BYTES ((2 * ASTAGE + 2 * BSTAGE) * 4)

template <int F>
__global__ void __launch_bounds__(256, 1) tgemm(
    const float* __restrict__ A, const float* __restrict__ B, float* __restrict__ C,
    int M, int N, int K, int lda, int ldb, int ldc,
    long sA, long sB, long sC,
    const float* __restrict__ bias,
    const float* __restrict__ res, long sRes,
    float alpha)
{
    extern __shared__ float sm[];
    float* As = sm;                 // 2 stages of [16][136]
    float* Bs = sm + 2 * ASTAGE;    // 2 stages of [16][264]

    const int bz = blockIdx.z;
    const int n0 = blockIdx.x * 256;
    const int m0 = blockIdx.y * 128;
    const int tid = threadIdx.x;
    const int warp = tid >> 5;
    const int lane = tid & 31;
    const int wm = warp & 1;       // 2 warps along M
    const int wn = warp >> 1;      // 4 warps along N
    const int g = lane >> 2;       // 0..7
    const int tg = lane & 3;       // 0..3

    const float* Ab = A + (size_t)bz * sA;
    const float* Bb = B + (size_t)bz * sB;

    float acc[4][8][4];
    #pragma unroll
    for (int i = 0; i < 4; i++)
        #pragma unroll
        for (int j = 0; j < 8; j++)
            #pragma unroll
            for (int r = 0; r < 4; r++) acc[i][j][r] = 0.f;

    // stage loaders
    auto loadStage = [&](int st, int k0) {
        float* Ad = As + st * ASTAGE;
        float* Bd = Bs + st * BSTAGE;
        #pragma unroll
        for (int j = 0; j < 2; j++) {          // A: 512 chunks of 16B
            int id = tid + j * 256;
            int k = id >> 5, m4 = (id & 31) << 2;
            cpa16(Ad + k * ASTR + m4, Ab + (size_t)(k0 + k) * lda + m0 + m4);
        }
        #pragma unroll
        for (int j = 0; j < 4; j++) {          // B: 1024 chunks
            int id = tid + j * 256;
            int k = id >> 6, n4 = (id & 63) << 2;
            cpa16(Bd + k * BSTR + n4, Bb + (size_t)(k0 + k) * ldb + n0 + n4);
        }
        asm volatile("cp.async.commit_group;\n");
    };

    const int T = K >> 4;
    loadStage(0, 0);

    for (int t = 0; t < T; t++) {
        if (t + 1 < T) {
            loadStage((t + 1) & 1, (t + 1) << 4);
            asm volatile("cp.async.wait_group 1;\n");
        } else {
            asm volatile("cp.async.wait_group 0;\n");
        }
        __syncthreads();

        const float* Asb = As + (t & 1) * ASTAGE;
        const float* Bsb = Bs + (t & 1) * BSTAGE;
        #pragma unroll
        for (int kk = 0; kk < 16; kk += 8) {
            unsigned a[4][4], bfr[8][2];
            const int r0 = kk + tg;
            #pragma unroll
            for (int mi = 0; mi < 4; mi++) {
                int m = wm * 64 + mi * 16 + g;
                a[mi][0] = __float_as_uint(Asb[r0 * ASTR + m]);
                a[mi][1] = __float_as_uint(Asb[r0 * ASTR + m + 8]);
                a[mi][2] = __float_as_uint(Asb[(r0 + 4) * ASTR + m]);
                a[mi][3] = __float_as_uint(Asb[(r0 + 4) * ASTR + m + 8]);
            }
            #pragma unroll
            for (int ni = 0; ni < 8; ni++) {
                int n = wn * 64 + ni * 8 + g;
                bfr[ni][0] = __float_as_uint(Bsb[r0 * BSTR + n]);
                bfr[ni][1] = __float_as_uint(Bsb[(r0 + 4) * BSTR + n]);
            }
            #pragma unroll
            for (int mi = 0; mi < 4; mi++)
                #pragma unroll
                for (int ni = 0; ni < 8; ni++)
                    mma8(acc[mi][ni], a[mi], bfr[ni]);
        }
        __syncthreads();
    }

    // epilogue
    float* Cb = C + (size_t)bz * sC;
    const float* Rb = (F & F_ERES) ? (res + (size_t)bz * sRes) : nullptr;
    #pragma unroll
    for (int mi = 0; mi < 4; mi++) {
        int mr = m0 + wm * 64 + mi * 16 + g;    // rows mr, mr+8
        float bi0 = 0.f, bi8 = 0.f;
        if (F & F_EBIAS) { bi0 = bias[mr]; bi8 = bias[mr + 8]; }
        #pragma unroll
        for (int ni = 0; ni < 8; ni++) {
            int nc = n0 + wn * 64 + ni * 8 + tg * 2;
            float v0 = acc[mi][ni][0] * alpha + bi0;
            float v1 = acc[mi][ni][1] * alpha + bi0;
            float v2 = acc[mi][ni][2] * alpha + bi8;
            float v3 = acc[mi][ni][3] * alpha + bi8;
            if (F & F_ERES) {
                float2 rA = *(const float2*)(Rb + (size_t)mr * ldc + nc);
                float2 rB = *(const float2*)(Rb + (size_t)(mr + 8) * ldc + nc);
                v0 += rA.x; v1 += rA.y; v2 += rB.x; v3 += rB.y;
            }
            if (F & F_ERELU) {
                v0 = fmaxf(v0, 0.f); v1 = fmaxf(v1, 0.f);
                v2 = fmaxf(v2, 0.f); v3 = fmaxf(v3, 0.f);
            }
            if (F & F_EROUND) {
                v0 = rtf(v0); v1 = rtf(v1); v2 = rtf(v2); v3 = rtf(v3);
            }
            *(float2*)(Cb + (size_t)mr * ldc + nc) = make_float2(v0, v1);
            *(float2*)(Cb + (size_t)(mr + 8) * ldc + nc) = make_float2(v2, v3);
        }
    }
}

// ---------------- launcher ----------------
extern "C" void kernel_launch(void* const* d_in, const int* in_sizes, int n_in,
                              void* d_out, int out_size) {
    const float* x     = (const float*)d_in[0];
    const float* bn1_g = (const float*)d_in[1];
    const float* bn1_b = (const float*)d_in[2];
    const float* W_qkv = (const float*)d_in[3];
    const float* b_qkv = (const float*)d_in[4];
    const float* bn2_g = (const float*)d_in[5];
    const float* bn2_b = (const float*)d_in[6];
    const float* W1    = (const float*)d_in[7];
    const float* b1    = (const float*)d_in[8];
    const float* W2    = (const float*)d_in[9];
    const float* b2    = (const float*)d_in[10];
    float* out = (float*)d_out;

    float *p_qkv, *p_beta, *p_xr, *p_h, *p_vt, *p_z;
    float *p_wqkvt, *p_w1t, *p_w2t;
    float *p_s1, *p_h1, *p_s2, *p_h2;
    float *p_pmax, *p_psum, *p_cmax, *p_cinv;
    cudaGetSymbolAddress((void**)&p_qkv,   g_qkv);
    cudaGetSymbolAddress((void**)&p_beta,  g_beta);
    cudaGetSymbolAddress((void**)&p_xr,    g_xr);
    cudaGetSymbolAddress((void**)&p_h,     g_h);
    cudaGetSymbolAddress((void**)&p_vt,    g_vt);
    cudaGetSymbolAddress((void**)&p_z,     g_z);
    cudaGetSymbolAddress((void**)&p_wqkvt, g_wqkvt);
    cudaGetSymbolAddress((void**)&p_w1t,   g_w1t);
    cudaGetSymbolAddress((void**)&p_w2t,   g_w2t);
    cudaGetSymbolAddress((void**)&p_s1,    g_scale1);
    cudaGetSymbolAddress((void**)&p_h1,    g_shift1);
    cudaGetSymbolAddress((void**)&p_s2,    g_scale2);
    cudaGetSymbolAddress((void**)&p_h2,    g_shift2);
    cudaGetSymbolAddress((void**)&p_pmax,  g_pmax);
    cudaGetSymbolAddress((void**)&p_psum,  g_psum);
    cudaGetSymbolAddress((void**)&p_cmax,  g_cmax);
    cudaGetSymbolAddress((void**)&p_cinv,  g_cinv);

    // opt-in smem for the gemm instantiations (idempotent)
    cudaFuncSetAttribute(tgemm<F_EBIAS | F_EROUND>, cudaFuncAttributeMaxDynamicSharedMemorySize, SMEM_BYTES);
    cudaFuncSetAttribute(tgemm<0>,                  cudaFuncAttributeMaxDynamicSharedMemorySize, SMEM_BYTES);
    cudaFuncSetAttribute(tgemm<F_ERES>,             cudaFuncAttributeMaxDynamicSharedMemorySize, SMEM_BYTES);
    cudaFuncSetAttribute(tgemm<F_EBIAS | F_ERELU | F_EROUND>, cudaFuncAttributeMaxDynamicSharedMemorySize, SMEM_BYTES);
    cudaFuncSetAttribute(tgemm<F_EBIAS | F_ERES>,   cudaFuncAttributeMaxDynamicSharedMemorySize, SMEM_BYTES);

    const long sX = (long)CC * HW;
    const long sQ = (long)OO * HW;
    const long sS = (long)HW * HW;

    // 0) weight transposes (+tf32 rounding)
    transpose_rnd<<<dim3(16, 20, 1), dim3(32, 8)>>>(W_qkv, p_wqkvt, OO, CC, 0, 0);
    transpose_rnd<<<dim3(16, 16, 1), dim3(32, 8)>>>(W1, p_w1t, CC, CC, 0, 0);
    transpose_rnd<<<dim3(16, 16, 1), dim3(32, 8)>>>(W2, p_w2t, CC, CC, 0, 0);

    // 1) bn1 stats + h1 = rtf(relu(bn1(x)))
    bn_stats_kernel<<<CC, 256>>>(x, bn1_g, bn1_b, p_s1, p_h1);
    bn_apply<true><<<BB * CC * HW / 4 / 256, 256>>>(x, p_s1, p_h1, p_h);

    // 2) qkv = Wqkv @ h1 + b_qkv (rounded)
    tgemm<F_EBIAS | F_EROUND><<<dim3(4, 5, BB), 256, SMEM_BYTES>>>(
        p_wqkvt, p_h, p_qkv, OO, HW, CC, OO, HW, HW,
        0L, sX, sQ, b_qkv, nullptr, 0L, 1.0f);

    // 3) S = (Q^T K)/8
    tgemm<0><<<dim3(4, 8, BB), 256, SMEM_BYTES>>>(
        p_qkv, p_qkv + DD * HW, p_beta, HW, HW, DD, HW, HW, HW,
        sQ, sQ, sS, nullptr, nullptr, 0L, 0.125f);

    // 4) softmax stats + normalize P in place
    softmax_partial<<<dim3(4, 4, BB), 256>>>(p_beta, p_pmax, p_psum);
    softmax_combine<<<dim3(4, BB), 256>>>(p_pmax, p_psum, p_cmax, p_cinv);
    p_apply<<<(int)(sS * BB / 4 / 256), 256>>>(p_beta, p_cmax, p_cinv);

    // 5) Vt[b][q][c] = rtf(V[b][c][q])
    transpose_rnd<<<dim3(32, 16, BB), dim3(32, 8)>>>(
        p_qkv + 2 * DD * HW, p_vt, CC, HW, sQ, sX);

    // 6) xr = x + Vt^T P
    tgemm<F_ERES><<<dim3(4, 4, BB), 256, SMEM_BYTES>>>(
        p_vt, p_beta, p_xr, CC, HW, HW, CC, HW, HW,
        sX, sS, sX, nullptr, x, sX, 1.0f);

    // 7) bn2 stats + h2 = rtf(bn2(xr))
    bn_stats_kernel<<<CC, 256>>>(p_xr, bn2_g, bn2_b, p_s2, p_h2);
    bn_apply<false><<<BB * CC * HW / 4 / 256, 256>>>(p_xr, p_s2, p_h2, p_h);

    // 8) z = rtf(relu(W1 @ h2 + b1))
    tgemm<F_EBIAS | F_ERELU | F_EROUND><<<dim3(4, 4, BB), 256, SMEM_BYTES>>>(
        p_w1t, p_h, p_z, CC, HW, CC, CC, HW, HW,
        0L, sX, sX, b1, nullptr, 0L, 1.0f);

    // 9) out = xr + W2 @ z + b2
    tgemm<F_EBIAS | F_ERES><<<dim3(4, 4, BB), 256, SMEM_BYTES>>>(
        p_w2t, p_z, out, CC, HW, CC, CC, HW, HW,
        0L, sX, sX, b2, p_xr, sX, 1.0f);
}